// round 10
// baseline (speedup 1.0000x reference)
#include <cuda_runtime.h>
#include <cstdint>

// Codec_35785667510396 — fused autoregressive PixelPred + RMSE + dual histograms.
// R10: j-pair vectorization. f32x2 lanes = (v_j, v_j+1) of the SAME block;
// weights TRANSPOSED in smem (Wt[k][o][j]) so weight pairs are contiguous ->
// LDS.128 gives ready FFMA2 operands with ZERO duplication MOVs (inputs are
// adjacent in memory too). Horizontal add + scalar leaky per output; results
// land directly in next layer's pair slots. TPB=256, 2 blocks/thread.

typedef unsigned long long u64;

#define TPB 256
#define BLOCKS_PER_CTA 512
#define CHUNKS (65536 / BLOCKS_PER_CTA)  // 128
#define NBC 48

__device__ double g_sumsq;
__device__ unsigned int g_hist_x[NBC * 256];
__device__ unsigned int g_hist_d[NBC * 256];

__device__ __forceinline__ u64 pack2(float lo, float hi) {
    u64 r; asm("mov.b64 %0, {%1, %2};" : "=l"(r) : "f"(lo), "f"(hi)); return r;
}
__device__ __forceinline__ float2 unpack2(u64 v) {
    float2 f; asm("mov.b64 {%0, %1}, %2;" : "=f"(f.x), "=f"(f.y) : "l"(v)); return f;
}
__device__ __forceinline__ u64 ffma2(u64 a, u64 b, u64 c) {
    u64 d; asm("fma.rn.f32x2 %0, %1, %2, %3;" : "=l"(d) : "l"(a), "l"(b), "l"(c)); return d;
}
__device__ __forceinline__ u64 mul2(u64 a, u64 b) {
    u64 d; asm("mul.rn.f32x2 %0, %1, %2;" : "=l"(d) : "l"(a), "l"(b)); return d;
}

__device__ __forceinline__ float leaky1(float s) {
    return fmaxf(s, 0.01f * s);
}

__device__ __forceinline__ int binof(float v) {
    int t = (int)floorf((v + 1.0f) * 128.0f);
    t = max(t, 0); t = min(t, 255);
    return t;
}

// delta = x - clip(pred,-1,1); torch fmod(delta+1,2)-1 with t in [-1,3]
__device__ __forceinline__ float wrapdelta(float xv, float pred) {
    float p = fminf(fmaxf(pred, -1.0f), 1.0f);
    float t = (xv - p) + 1.0f;
    t = (t >= 2.0f) ? (t - 2.0f) : t;
    return t - 1.0f;
}

struct __align__(16) Smem {
    float W0t[16 * 12 * 16];  // [k][o][j], zero at j==k (3072)
    float W1t[16 * 12 * 12];  // [k][o][i] transposed (2304)
    float W2t[16 * 12 * 12];  // (2304)
    float W3v[16 * 12];       // [k][i] (natural layout already a vector)
    float b0s[16 * 12];
    float b1s[16 * 12];
    float b2s[16 * 12];
    float b3s[16];
    unsigned int hx[256];
    unsigned int hd[256];
    float warpsums[8];
};

__global__ void __launch_bounds__(TPB, 2) codec_main(
    const float* __restrict__ x,
    const float* __restrict__ W0, const float* __restrict__ b0,
    const float* __restrict__ W1, const float* __restrict__ b1,
    const float* __restrict__ W2, const float* __restrict__ b2,
    const float* __restrict__ W3, const float* __restrict__ b3)
{
    __shared__ Smem s;
    const int tid = threadIdx.x;
    const int bc = blockIdx.x / CHUNKS;     // 0..47  (= b*3 + c)
    const int chunk = blockIdx.x % CHUNKS;
    const int c = bc % 3;

    // ---- transpose-load weights into smem ----
    // W0t[k][o][j]: zero at j==k; else W0[c][k][ j-(j>k) ][o]
    for (int idx = tid; idx < 16 * 12 * 16; idx += TPB) {
        int k = idx / 192; int r = idx % 192; int o = r / 16; int j = r % 16;
        float w = 0.0f;
        if (j != k) {
            int i = j - (j > k);
            w = W0[((c * 16 + k) * 15 + i) * 12 + o];
        }
        s.W0t[idx] = w;
    }
    // W1t/W2t[k][o][i] = W[c][k][i][o]
    for (int idx = tid; idx < 16 * 12 * 12; idx += TPB) {
        int k = idx / 144; int r = idx % 144; int o = r / 12; int i = r % 12;
        s.W1t[idx] = W1[c * 2304 + k * 144 + i * 12 + o];
        s.W2t[idx] = W2[c * 2304 + k * 144 + i * 12 + o];
    }
    for (int idx = tid; idx < 192; idx += TPB) {
        s.W3v[idx] = W3[c * 192 + idx];   // [k][i][0] -> [k][i]
        s.b0s[idx] = b0[c * 192 + idx];
        s.b1s[idx] = b1[c * 192 + idx];
        s.b2s[idx] = b2[c * 192 + idx];
    }
    if (tid < 16) s.b3s[tid] = b3[c * 16 + tid];
    s.hx[tid] = 0;
    s.hd[tid] = 0;
    __syncthreads();

    // ---- load 2 blocks of 16 pixels as 8 adjacent-pixel pairs each ----
    const float* xb = x + (size_t)bc * (1024 * 1024);
    const int n0 = chunk * BLOCKS_PER_CTA + tid;
    const int n1 = n0 + TPB;
    const float* pA = xb + ((n0 >> 8) * 4096) + ((n0 & 255) * 4);
    const float* pB = xb + ((n1 >> 8) * 4096) + ((n1 & 255) * 4);

    u64 vpA[8], vpB[8];
#pragma unroll
    for (int r = 0; r < 4; r++) {
        ulonglong2 a = *(const ulonglong2*)(pA + r * 1024);  // (x0,x1),(x2,x3)
        ulonglong2 b = *(const ulonglong2*)(pB + r * 1024);
        vpA[r * 2 + 0] = a.x; vpA[r * 2 + 1] = a.y;
        vpB[r * 2 + 0] = b.x; vpB[r * 2 + 1] = b.y;
    }

    // ---- histogram of raw x ----
#pragma unroll
    for (int jp = 0; jp < 8; jp++) {
        float2 fa = unpack2(vpA[jp]);
        float2 fb = unpack2(vpB[jp]);
        atomicAdd(&s.hx[binof(fa.x)], 1u);
        atomicAdd(&s.hx[binof(fa.y)], 1u);
        atomicAdd(&s.hx[binof(fb.x)], 1u);
        atomicAdd(&s.hx[binof(fb.y)], 1u);
    }

    // ---- autoregressive 16-step MLP chain ----
    float sq = 0.0f;
#pragma unroll 1
    for (int k = 0; k < 16; k++) {
        const float* W0k = s.W0t + k * 192;
        const float* W1k = s.W1t + k * 144;
        const float* W2k = s.W2t + k * 144;

        u64 accA[12], accB[12];
        u64 hA[6], hB[6];

        // ---- layer 0: 16 inputs (8 pairs, zero row at j==k) x 12 outputs ----
#pragma unroll
        for (int o = 0; o < 12; o++) {
            const ulonglong2* wr = (const ulonglong2*)(W0k + o * 16);
            ulonglong2 wa = wr[0], wb = wr[1], wc = wr[2], wd = wr[3];
            u64 aA = mul2(wa.x, vpA[0]);
            u64 aB = mul2(wa.x, vpB[0]);
            aA = ffma2(wa.y, vpA[1], aA);  aB = ffma2(wa.y, vpB[1], aB);
            aA = ffma2(wb.x, vpA[2], aA);  aB = ffma2(wb.x, vpB[2], aB);
            aA = ffma2(wb.y, vpA[3], aA);  aB = ffma2(wb.y, vpB[3], aB);
            aA = ffma2(wc.x, vpA[4], aA);  aB = ffma2(wc.x, vpB[4], aB);
            aA = ffma2(wc.y, vpA[5], aA);  aB = ffma2(wc.y, vpB[5], aB);
            aA = ffma2(wd.x, vpA[6], aA);  aB = ffma2(wd.x, vpB[6], aB);
            aA = ffma2(wd.y, vpA[7], aA);  aB = ffma2(wd.y, vpB[7], aB);
            accA[o] = aA; accB[o] = aB;
        }
        {
            const float4* bp = (const float4*)(s.b0s + k * 12);
            float4 q0 = bp[0], q1 = bp[1], q2 = bp[2];
            float bb[12] = {q0.x, q0.y, q0.z, q0.w, q1.x, q1.y, q1.z, q1.w,
                            q2.x, q2.y, q2.z, q2.w};
#pragma unroll
            for (int p = 0; p < 6; p++) {
                float2 a0 = unpack2(accA[2 * p]), a1 = unpack2(accA[2 * p + 1]);
                hA[p] = pack2(leaky1(a0.x + a0.y + bb[2 * p]),
                              leaky1(a1.x + a1.y + bb[2 * p + 1]));
                float2 c0 = unpack2(accB[2 * p]), c1 = unpack2(accB[2 * p + 1]);
                hB[p] = pack2(leaky1(c0.x + c0.y + bb[2 * p]),
                              leaky1(c1.x + c1.y + bb[2 * p + 1]));
            }
        }

        // ---- layer 1: 12 x 12 ----
#pragma unroll
        for (int o = 0; o < 12; o++) {
            const ulonglong2* wr = (const ulonglong2*)(W1k + o * 12);
            ulonglong2 wa = wr[0], wb = wr[1];
            u64 wc_ = *(const u64*)(W1k + o * 12 + 8);
            u64 wd_ = *(const u64*)(W1k + o * 12 + 10);
            u64 aA = mul2(wa.x, hA[0]);
            u64 aB = mul2(wa.x, hB[0]);
            aA = ffma2(wa.y, hA[1], aA);  aB = ffma2(wa.y, hB[1], aB);
            aA = ffma2(wb.x, hA[2], aA);  aB = ffma2(wb.x, hB[2], aB);
            aA = ffma2(wb.y, hA[3], aA);  aB = ffma2(wb.y, hB[3], aB);
            aA = ffma2(wc_, hA[4], aA);   aB = ffma2(wc_, hB[4], aB);
            aA = ffma2(wd_, hA[5], aA);   aB = ffma2(wd_, hB[5], aB);
            accA[o] = aA; accB[o] = aB;
        }
        {
            const float4* bp = (const float4*)(s.b1s + k * 12);
            float4 q0 = bp[0], q1 = bp[1], q2 = bp[2];
            float bb[12] = {q0.x, q0.y, q0.z, q0.w, q1.x, q1.y, q1.z, q1.w,
                            q2.x, q2.y, q2.z, q2.w};
#pragma unroll
            for (int p = 0; p < 6; p++) {
                float2 a0 = unpack2(accA[2 * p]), a1 = unpack2(accA[2 * p + 1]);
                hA[p] = pack2(leaky1(a0.x + a0.y + bb[2 * p]),
                              leaky1(a1.x + a1.y + bb[2 * p + 1]));
                float2 c0 = unpack2(accB[2 * p]), c1 = unpack2(accB[2 * p + 1]);
                hB[p] = pack2(leaky1(c0.x + c0.y + bb[2 * p]),
                              leaky1(c1.x + c1.y + bb[2 * p + 1]));
            }
        }

        // ---- layer 2: 12 x 12 ----
#pragma unroll
        for (int o = 0; o < 12; o++) {
            const ulonglong2* wr = (const ulonglong2*)(W2k + o * 12);
            ulonglong2 wa = wr[0], wb = wr[1];
            u64 wc_ = *(const u64*)(W2k + o * 12 + 8);
            u64 wd_ = *(const u64*)(W2k + o * 12 + 10);
            u64 aA = mul2(wa.x, hA[0]);
            u64 aB = mul2(wa.x, hB[0]);
            aA = ffma2(wa.y, hA[1], aA);  aB = ffma2(wa.y, hB[1], aB);
            aA = ffma2(wb.x, hA[2], aA);  aB = ffma2(wb.x, hB[2], aB);
            aA = ffma2(wb.y, hA[3], aA);  aB = ffma2(wb.y, hB[3], aB);
            aA = ffma2(wc_, hA[4], aA);   aB = ffma2(wc_, hB[4], aB);
            aA = ffma2(wd_, hA[5], aA);   aB = ffma2(wd_, hB[5], aB);
            accA[o] = aA; accB[o] = aB;
        }
        {
            const float4* bp = (const float4*)(s.b2s + k * 12);
            float4 q0 = bp[0], q1 = bp[1], q2 = bp[2];
            float bb[12] = {q0.x, q0.y, q0.z, q0.w, q1.x, q1.y, q1.z, q1.w,
                            q2.x, q2.y, q2.z, q2.w};
#pragma unroll
            for (int p = 0; p < 6; p++) {
                float2 a0 = unpack2(accA[2 * p]), a1 = unpack2(accA[2 * p + 1]);
                hA[p] = pack2(leaky1(a0.x + a0.y + bb[2 * p]),
                              leaky1(a1.x + a1.y + bb[2 * p + 1]));
                float2 c0 = unpack2(accB[2 * p]), c1 = unpack2(accB[2 * p + 1]);
                hB[p] = pack2(leaky1(c0.x + c0.y + bb[2 * p]),
                              leaky1(c1.x + c1.y + bb[2 * p + 1]));
            }
        }

        // ---- layer 3: 12 -> 1 ----
        float predA, predB;
        {
            const ulonglong2* wr = (const ulonglong2*)(s.W3v + k * 12);
            ulonglong2 wa = wr[0], wb = wr[1];
            u64 wc_ = *(const u64*)(s.W3v + k * 12 + 8);
            u64 wd_ = *(const u64*)(s.W3v + k * 12 + 10);
            u64 aA = mul2(wa.x, hA[0]);
            u64 aB = mul2(wa.x, hB[0]);
            aA = ffma2(wa.y, hA[1], aA);  aB = ffma2(wa.y, hB[1], aB);
            aA = ffma2(wb.x, hA[2], aA);  aB = ffma2(wb.x, hB[2], aB);
            aA = ffma2(wb.y, hA[3], aA);  aB = ffma2(wb.y, hB[3], aB);
            aA = ffma2(wc_, hA[4], aA);   aB = ffma2(wc_, hB[4], aB);
            aA = ffma2(wd_, hA[5], aA);   aB = ffma2(wd_, hB[5], aB);
            float b3s = s.b3s[k];
            float2 fA = unpack2(aA);
            float2 fB = unpack2(aB);
            predA = fA.x + fA.y + b3s;
            predB = fB.x + fB.y + b3s;
        }

        // ---- delta, hist, writeback ----
        const int kp = k >> 1;
        const int kh = k & 1;

        u64 xpA = vpA[0], xpB = vpB[0];
#pragma unroll
        for (int jp = 1; jp < 8; jp++) if (jp == kp) { xpA = vpA[jp]; xpB = vpB[jp]; }
        float2 xfA = unpack2(xpA);
        float2 xfB = unpack2(xpB);
        float xkA = kh ? xfA.y : xfA.x;
        float xkB = kh ? xfB.y : xfB.x;

        float eA = wrapdelta(xkA, predA);
        float eB = wrapdelta(xkB, predB);
        sq += eA * eA + eB * eB;
        atomicAdd(&s.hd[binof(eA)], 1u);
        atomicAdd(&s.hd[binof(eB)], 1u);

        u64 npA = kh ? pack2(xfA.x, eA) : pack2(eA, xfA.y);
        u64 npB = kh ? pack2(xfB.x, eB) : pack2(eB, xfB.y);
#pragma unroll
        for (int jp = 0; jp < 8; jp++) if (jp == kp) { vpA[jp] = npA; vpB[jp] = npB; }
    }

    // ---- reductions ----
#pragma unroll
    for (int off = 16; off; off >>= 1) sq += __shfl_xor_sync(0xFFFFFFFFu, sq, off);
    if ((tid & 31) == 0) s.warpsums[tid >> 5] = sq;
    __syncthreads();
    if (tid == 0) {
        float t = 0.0f;
#pragma unroll
        for (int w = 0; w < 8; w++) t += s.warpsums[w];
        atomicAdd(&g_sumsq, (double)t);
    }
    atomicAdd(&g_hist_x[bc * 256 + tid], s.hx[tid]);
    atomicAdd(&g_hist_d[bc * 256 + tid], s.hd[tid]);
}

__global__ void codec_zero() {
    int t = blockIdx.x * blockDim.x + threadIdx.x;
    if (t < NBC * 256) { g_hist_x[t] = 0; g_hist_d[t] = 0; }
    if (t == 0) g_sumsq = 0.0;
}

__global__ void codec_final(float* __restrict__ out) {
    __shared__ double red[256];
    const int t = threadIdx.x;
    const float invres = 1.0f / 1048576.0f;
    double ex = 0.0, ed = 0.0;
    for (int i = t; i < NBC * 256; i += 256) {
        float px = (float)g_hist_x[i] * invres;
        if (px > 0.0f) ex += (double)(-px * log2f(px));
        float pd = (float)g_hist_d[i] * invres;
        if (pd > 0.0f) ed += (double)(-pd * log2f(pd));
    }
    red[t] = ex;
    __syncthreads();
    for (int sft = 128; sft; sft >>= 1) {
        if (t < sft) red[t] += red[t + sft];
        __syncthreads();
    }
    double entx = red[0];
    __syncthreads();
    red[t] = ed;
    __syncthreads();
    for (int sft = 128; sft; sft >>= 1) {
        if (t < sft) red[t] += red[t + sft];
        __syncthreads();
    }
    double entd = red[0];
    if (t == 0) {
        double mean = g_sumsq / 50331648.0;   // 16*3*65536*16
        out[0] = 255.0f * (float)sqrt(mean);
        out[1] = (float)(entx / 384.0);       // 8 * nch, nch=48
        out[2] = (float)(entd / 384.0);
    }
}

extern "C" void kernel_launch(void* const* d_in, const int* in_sizes, int n_in,
                              void* d_out, int out_size) {
    const float* x  = (const float*)d_in[0];
    const float* W0 = (const float*)d_in[1];
    const float* b0 = (const float*)d_in[2];
    const float* W1 = (const float*)d_in[3];
    const float* b1 = (const float*)d_in[4];
    const float* W2 = (const float*)d_in[5];
    const float* b2 = (const float*)d_in[6];
    const float* W3 = (const float*)d_in[7];
    const float* b3 = (const float*)d_in[8];

    codec_zero<<<NBC, 256>>>();
    codec_main<<<NBC * CHUNKS, TPB>>>(x, W0, b0, W1, b1, W2, b2, W3, b3);
    codec_final<<<1, 256>>>((float*)d_out);
}

// round 11
// speedup vs baseline: 1.0003x; 1.0003x over previous
#include <cuda_runtime.h>
#include <cstdint>

// Codec_35785667510396 — fused autoregressive PixelPred + RMSE + dual histograms.
// R10: j-pair vectorization. f32x2 lanes = (v_j, v_j+1) of the SAME block;
// weights TRANSPOSED in smem (Wt[k][o][j]) so weight pairs are contiguous ->
// LDS.128 gives ready FFMA2 operands with ZERO duplication MOVs (inputs are
// adjacent in memory too). Horizontal add + scalar leaky per output; results
// land directly in next layer's pair slots. TPB=256, 2 blocks/thread.

typedef unsigned long long u64;

#define TPB 256
#define BLOCKS_PER_CTA 512
#define CHUNKS (65536 / BLOCKS_PER_CTA)  // 128
#define NBC 48

__device__ double g_sumsq;
__device__ unsigned int g_hist_x[NBC * 256];
__device__ unsigned int g_hist_d[NBC * 256];

__device__ __forceinline__ u64 pack2(float lo, float hi) {
    u64 r; asm("mov.b64 %0, {%1, %2};" : "=l"(r) : "f"(lo), "f"(hi)); return r;
}
__device__ __forceinline__ float2 unpack2(u64 v) {
    float2 f; asm("mov.b64 {%0, %1}, %2;" : "=f"(f.x), "=f"(f.y) : "l"(v)); return f;
}
__device__ __forceinline__ u64 ffma2(u64 a, u64 b, u64 c) {
    u64 d; asm("fma.rn.f32x2 %0, %1, %2, %3;" : "=l"(d) : "l"(a), "l"(b), "l"(c)); return d;
}
__device__ __forceinline__ u64 mul2(u64 a, u64 b) {
    u64 d; asm("mul.rn.f32x2 %0, %1, %2;" : "=l"(d) : "l"(a), "l"(b)); return d;
}

__device__ __forceinline__ float leaky1(float s) {
    return fmaxf(s, 0.01f * s);
}

__device__ __forceinline__ int binof(float v) {
    int t = (int)floorf((v + 1.0f) * 128.0f);
    t = max(t, 0); t = min(t, 255);
    return t;
}

// delta = x - clip(pred,-1,1); torch fmod(delta+1,2)-1 with t in [-1,3]
__device__ __forceinline__ float wrapdelta(float xv, float pred) {
    float p = fminf(fmaxf(pred, -1.0f), 1.0f);
    float t = (xv - p) + 1.0f;
    t = (t >= 2.0f) ? (t - 2.0f) : t;
    return t - 1.0f;
}

struct __align__(16) Smem {
    float W0t[16 * 12 * 16];  // [k][o][j], zero at j==k (3072)
    float W1t[16 * 12 * 12];  // [k][o][i] transposed (2304)
    float W2t[16 * 12 * 12];  // (2304)
    float W3v[16 * 12];       // [k][i] (natural layout already a vector)
    float b0s[16 * 12];
    float b1s[16 * 12];
    float b2s[16 * 12];
    float b3s[16];
    unsigned int hx[256];
    unsigned int hd[256];
    float warpsums[8];
};

__global__ void __launch_bounds__(TPB, 2) codec_main(
    const float* __restrict__ x,
    const float* __restrict__ W0, const float* __restrict__ b0,
    const float* __restrict__ W1, const float* __restrict__ b1,
    const float* __restrict__ W2, const float* __restrict__ b2,
    const float* __restrict__ W3, const float* __restrict__ b3)
{
    __shared__ Smem s;
    const int tid = threadIdx.x;
    const int bc = blockIdx.x / CHUNKS;     // 0..47  (= b*3 + c)
    const int chunk = blockIdx.x % CHUNKS;
    const int c = bc % 3;

    // ---- transpose-load weights into smem ----
    // W0t[k][o][j]: zero at j==k; else W0[c][k][ j-(j>k) ][o]
    for (int idx = tid; idx < 16 * 12 * 16; idx += TPB) {
        int k = idx / 192; int r = idx % 192; int o = r / 16; int j = r % 16;
        float w = 0.0f;
        if (j != k) {
            int i = j - (j > k);
            w = W0[((c * 16 + k) * 15 + i) * 12 + o];
        }
        s.W0t[idx] = w;
    }
    // W1t/W2t[k][o][i] = W[c][k][i][o]
    for (int idx = tid; idx < 16 * 12 * 12; idx += TPB) {
        int k = idx / 144; int r = idx % 144; int o = r / 12; int i = r % 12;
        s.W1t[idx] = W1[c * 2304 + k * 144 + i * 12 + o];
        s.W2t[idx] = W2[c * 2304 + k * 144 + i * 12 + o];
    }
    for (int idx = tid; idx < 192; idx += TPB) {
        s.W3v[idx] = W3[c * 192 + idx];   // [k][i][0] -> [k][i]
        s.b0s[idx] = b0[c * 192 + idx];
        s.b1s[idx] = b1[c * 192 + idx];
        s.b2s[idx] = b2[c * 192 + idx];
    }
    if (tid < 16) s.b3s[tid] = b3[c * 16 + tid];
    s.hx[tid] = 0;
    s.hd[tid] = 0;
    __syncthreads();

    // ---- load 2 blocks of 16 pixels as 8 adjacent-pixel pairs each ----
    const float* xb = x + (size_t)bc * (1024 * 1024);
    const int n0 = chunk * BLOCKS_PER_CTA + tid;
    const int n1 = n0 + TPB;
    const float* pA = xb + ((n0 >> 8) * 4096) + ((n0 & 255) * 4);
    const float* pB = xb + ((n1 >> 8) * 4096) + ((n1 & 255) * 4);

    u64 vpA[8], vpB[8];
#pragma unroll
    for (int r = 0; r < 4; r++) {
        ulonglong2 a = *(const ulonglong2*)(pA + r * 1024);  // (x0,x1),(x2,x3)
        ulonglong2 b = *(const ulonglong2*)(pB + r * 1024);
        vpA[r * 2 + 0] = a.x; vpA[r * 2 + 1] = a.y;
        vpB[r * 2 + 0] = b.x; vpB[r * 2 + 1] = b.y;
    }

    // ---- histogram of raw x ----
#pragma unroll
    for (int jp = 0; jp < 8; jp++) {
        float2 fa = unpack2(vpA[jp]);
        float2 fb = unpack2(vpB[jp]);
        atomicAdd(&s.hx[binof(fa.x)], 1u);
        atomicAdd(&s.hx[binof(fa.y)], 1u);
        atomicAdd(&s.hx[binof(fb.x)], 1u);
        atomicAdd(&s.hx[binof(fb.y)], 1u);
    }

    // ---- autoregressive 16-step MLP chain ----
    float sq = 0.0f;
#pragma unroll 1
    for (int k = 0; k < 16; k++) {
        const float* W0k = s.W0t + k * 192;
        const float* W1k = s.W1t + k * 144;
        const float* W2k = s.W2t + k * 144;

        u64 accA[12], accB[12];
        u64 hA[6], hB[6];

        // ---- layer 0: 16 inputs (8 pairs, zero row at j==k) x 12 outputs ----
#pragma unroll
        for (int o = 0; o < 12; o++) {
            const ulonglong2* wr = (const ulonglong2*)(W0k + o * 16);
            ulonglong2 wa = wr[0], wb = wr[1], wc = wr[2], wd = wr[3];
            u64 aA = mul2(wa.x, vpA[0]);
            u64 aB = mul2(wa.x, vpB[0]);
            aA = ffma2(wa.y, vpA[1], aA);  aB = ffma2(wa.y, vpB[1], aB);
            aA = ffma2(wb.x, vpA[2], aA);  aB = ffma2(wb.x, vpB[2], aB);
            aA = ffma2(wb.y, vpA[3], aA);  aB = ffma2(wb.y, vpB[3], aB);
            aA = ffma2(wc.x, vpA[4], aA);  aB = ffma2(wc.x, vpB[4], aB);
            aA = ffma2(wc.y, vpA[5], aA);  aB = ffma2(wc.y, vpB[5], aB);
            aA = ffma2(wd.x, vpA[6], aA);  aB = ffma2(wd.x, vpB[6], aB);
            aA = ffma2(wd.y, vpA[7], aA);  aB = ffma2(wd.y, vpB[7], aB);
            accA[o] = aA; accB[o] = aB;
        }
        {
            const float4* bp = (const float4*)(s.b0s + k * 12);
            float4 q0 = bp[0], q1 = bp[1], q2 = bp[2];
            float bb[12] = {q0.x, q0.y, q0.z, q0.w, q1.x, q1.y, q1.z, q1.w,
                            q2.x, q2.y, q2.z, q2.w};
#pragma unroll
            for (int p = 0; p < 6; p++) {
                float2 a0 = unpack2(accA[2 * p]), a1 = unpack2(accA[2 * p + 1]);
                hA[p] = pack2(leaky1(a0.x + a0.y + bb[2 * p]),
                              leaky1(a1.x + a1.y + bb[2 * p + 1]));
                float2 c0 = unpack2(accB[2 * p]), c1 = unpack2(accB[2 * p + 1]);
                hB[p] = pack2(leaky1(c0.x + c0.y + bb[2 * p]),
                              leaky1(c1.x + c1.y + bb[2 * p + 1]));
            }
        }

        // ---- layer 1: 12 x 12 ----
#pragma unroll
        for (int o = 0; o < 12; o++) {
            const ulonglong2* wr = (const ulonglong2*)(W1k + o * 12);
            ulonglong2 wa = wr[0], wb = wr[1];
            u64 wc_ = *(const u64*)(W1k + o * 12 + 8);
            u64 wd_ = *(const u64*)(W1k + o * 12 + 10);
            u64 aA = mul2(wa.x, hA[0]);
            u64 aB = mul2(wa.x, hB[0]);
            aA = ffma2(wa.y, hA[1], aA);  aB = ffma2(wa.y, hB[1], aB);
            aA = ffma2(wb.x, hA[2], aA);  aB = ffma2(wb.x, hB[2], aB);
            aA = ffma2(wb.y, hA[3], aA);  aB = ffma2(wb.y, hB[3], aB);
            aA = ffma2(wc_, hA[4], aA);   aB = ffma2(wc_, hB[4], aB);
            aA = ffma2(wd_, hA[5], aA);   aB = ffma2(wd_, hB[5], aB);
            accA[o] = aA; accB[o] = aB;
        }
        {
            const float4* bp = (const float4*)(s.b1s + k * 12);
            float4 q0 = bp[0], q1 = bp[1], q2 = bp[2];
            float bb[12] = {q0.x, q0.y, q0.z, q0.w, q1.x, q1.y, q1.z, q1.w,
                            q2.x, q2.y, q2.z, q2.w};
#pragma unroll
            for (int p = 0; p < 6; p++) {
                float2 a0 = unpack2(accA[2 * p]), a1 = unpack2(accA[2 * p + 1]);
                hA[p] = pack2(leaky1(a0.x + a0.y + bb[2 * p]),
                              leaky1(a1.x + a1.y + bb[2 * p + 1]));
                float2 c0 = unpack2(accB[2 * p]), c1 = unpack2(accB[2 * p + 1]);
                hB[p] = pack2(leaky1(c0.x + c0.y + bb[2 * p]),
                              leaky1(c1.x + c1.y + bb[2 * p + 1]));
            }
        }

        // ---- layer 2: 12 x 12 ----
#pragma unroll
        for (int o = 0; o < 12; o++) {
            const ulonglong2* wr = (const ulonglong2*)(W2k + o * 12);
            ulonglong2 wa = wr[0], wb = wr[1];
            u64 wc_ = *(const u64*)(W2k + o * 12 + 8);
            u64 wd_ = *(const u64*)(W2k + o * 12 + 10);
            u64 aA = mul2(wa.x, hA[0]);
            u64 aB = mul2(wa.x, hB[0]);
            aA = ffma2(wa.y, hA[1], aA);  aB = ffma2(wa.y, hB[1], aB);
            aA = ffma2(wb.x, hA[2], aA);  aB = ffma2(wb.x, hB[2], aB);
            aA = ffma2(wb.y, hA[3], aA);  aB = ffma2(wb.y, hB[3], aB);
            aA = ffma2(wc_, hA[4], aA);   aB = ffma2(wc_, hB[4], aB);
            aA = ffma2(wd_, hA[5], aA);   aB = ffma2(wd_, hB[5], aB);
            accA[o] = aA; accB[o] = aB;
        }
        {
            const float4* bp = (const float4*)(s.b2s + k * 12);
            float4 q0 = bp[0], q1 = bp[1], q2 = bp[2];
            float bb[12] = {q0.x, q0.y, q0.z, q0.w, q1.x, q1.y, q1.z, q1.w,
                            q2.x, q2.y, q2.z, q2.w};
#pragma unroll
            for (int p = 0; p < 6; p++) {
                float2 a0 = unpack2(accA[2 * p]), a1 = unpack2(accA[2 * p + 1]);
                hA[p] = pack2(leaky1(a0.x + a0.y + bb[2 * p]),
                              leaky1(a1.x + a1.y + bb[2 * p + 1]));
                float2 c0 = unpack2(accB[2 * p]), c1 = unpack2(accB[2 * p + 1]);
                hB[p] = pack2(leaky1(c0.x + c0.y + bb[2 * p]),
                              leaky1(c1.x + c1.y + bb[2 * p + 1]));
            }
        }

        // ---- layer 3: 12 -> 1 ----
        float predA, predB;
        {
            const ulonglong2* wr = (const ulonglong2*)(s.W3v + k * 12);
            ulonglong2 wa = wr[0], wb = wr[1];
            u64 wc_ = *(const u64*)(s.W3v + k * 12 + 8);
            u64 wd_ = *(const u64*)(s.W3v + k * 12 + 10);
            u64 aA = mul2(wa.x, hA[0]);
            u64 aB = mul2(wa.x, hB[0]);
            aA = ffma2(wa.y, hA[1], aA);  aB = ffma2(wa.y, hB[1], aB);
            aA = ffma2(wb.x, hA[2], aA);  aB = ffma2(wb.x, hB[2], aB);
            aA = ffma2(wb.y, hA[3], aA);  aB = ffma2(wb.y, hB[3], aB);
            aA = ffma2(wc_, hA[4], aA);   aB = ffma2(wc_, hB[4], aB);
            aA = ffma2(wd_, hA[5], aA);   aB = ffma2(wd_, hB[5], aB);
            float b3s = s.b3s[k];
            float2 fA = unpack2(aA);
            float2 fB = unpack2(aB);
            predA = fA.x + fA.y + b3s;
            predB = fB.x + fB.y + b3s;
        }

        // ---- delta, hist, writeback ----
        const int kp = k >> 1;
        const int kh = k & 1;

        u64 xpA = vpA[0], xpB = vpB[0];
#pragma unroll
        for (int jp = 1; jp < 8; jp++) if (jp == kp) { xpA = vpA[jp]; xpB = vpB[jp]; }
        float2 xfA = unpack2(xpA);
        float2 xfB = unpack2(xpB);
        float xkA = kh ? xfA.y : xfA.x;
        float xkB = kh ? xfB.y : xfB.x;

        float eA = wrapdelta(xkA, predA);
        float eB = wrapdelta(xkB, predB);
        sq += eA * eA + eB * eB;
        atomicAdd(&s.hd[binof(eA)], 1u);
        atomicAdd(&s.hd[binof(eB)], 1u);

        u64 npA = kh ? pack2(xfA.x, eA) : pack2(eA, xfA.y);
        u64 npB = kh ? pack2(xfB.x, eB) : pack2(eB, xfB.y);
#pragma unroll
        for (int jp = 0; jp < 8; jp++) if (jp == kp) { vpA[jp] = npA; vpB[jp] = npB; }
    }

    // ---- reductions ----
#pragma unroll
    for (int off = 16; off; off >>= 1) sq += __shfl_xor_sync(0xFFFFFFFFu, sq, off);
    if ((tid & 31) == 0) s.warpsums[tid >> 5] = sq;
    __syncthreads();
    if (tid == 0) {
        float t = 0.0f;
#pragma unroll
        for (int w = 0; w < 8; w++) t += s.warpsums[w];
        atomicAdd(&g_sumsq, (double)t);
    }
    atomicAdd(&g_hist_x[bc * 256 + tid], s.hx[tid]);
    atomicAdd(&g_hist_d[bc * 256 + tid], s.hd[tid]);
}

__global__ void codec_zero() {
    int t = blockIdx.x * blockDim.x + threadIdx.x;
    if (t < NBC * 256) { g_hist_x[t] = 0; g_hist_d[t] = 0; }
    if (t == 0) g_sumsq = 0.0;
}

__global__ void codec_final(float* __restrict__ out) {
    __shared__ double red[256];
    const int t = threadIdx.x;
    const float invres = 1.0f / 1048576.0f;
    double ex = 0.0, ed = 0.0;
    for (int i = t; i < NBC * 256; i += 256) {
        float px = (float)g_hist_x[i] * invres;
        if (px > 0.0f) ex += (double)(-px * log2f(px));
        float pd = (float)g_hist_d[i] * invres;
        if (pd > 0.0f) ed += (double)(-pd * log2f(pd));
    }
    red[t] = ex;
    __syncthreads();
    for (int sft = 128; sft; sft >>= 1) {
        if (t < sft) red[t] += red[t + sft];
        __syncthreads();
    }
    double entx = red[0];
    __syncthreads();
    red[t] = ed;
    __syncthreads();
    for (int sft = 128; sft; sft >>= 1) {
        if (t < sft) red[t] += red[t + sft];
        __syncthreads();
    }
    double entd = red[0];
    if (t == 0) {
        double mean = g_sumsq / 50331648.0;   // 16*3*65536*16
        out[0] = 255.0f * (float)sqrt(mean);
        out[1] = (float)(entx / 384.0);       // 8 * nch, nch=48
        out[2] = (float)(entd / 384.0);
    }
}

extern "C" void kernel_launch(void* const* d_in, const int* in_sizes, int n_in,
                              void* d_out, int out_size) {
    const float* x  = (const float*)d_in[0];
    const float* W0 = (const float*)d_in[1];
    const float* b0 = (const float*)d_in[2];
    const float* W1 = (const float*)d_in[3];
    const float* b1 = (const float*)d_in[4];
    const float* W2 = (const float*)d_in[5];
    const float* b2 = (const float*)d_in[6];
    const float* W3 = (const float*)d_in[7];
    const float* b3 = (const float*)d_in[8];

    codec_zero<<<NBC, 256>>>();
    codec_main<<<NBC * CHUNKS, TPB>>>(x, W0, b0, W1, b1, W2, b2, W3, b3);
    codec_final<<<1, 256>>>((float*)d_out);
}

// round 12
// speedup vs baseline: 1.0005x; 1.0002x over previous
#include <cuda_runtime.h>
#include <cstdint>

// Codec_35785667510396 — fused autoregressive PixelPred + RMSE + dual histograms.
// R10: j-pair vectorization. f32x2 lanes = (v_j, v_j+1) of the SAME block;
// weights TRANSPOSED in smem (Wt[k][o][j]) so weight pairs are contiguous ->
// LDS.128 gives ready FFMA2 operands with ZERO duplication MOVs (inputs are
// adjacent in memory too). Horizontal add + scalar leaky per output; results
// land directly in next layer's pair slots. TPB=256, 2 blocks/thread.

typedef unsigned long long u64;

#define TPB 256
#define BLOCKS_PER_CTA 512
#define CHUNKS (65536 / BLOCKS_PER_CTA)  // 128
#define NBC 48

__device__ double g_sumsq;
__device__ unsigned int g_hist_x[NBC * 256];
__device__ unsigned int g_hist_d[NBC * 256];

__device__ __forceinline__ u64 pack2(float lo, float hi) {
    u64 r; asm("mov.b64 %0, {%1, %2};" : "=l"(r) : "f"(lo), "f"(hi)); return r;
}
__device__ __forceinline__ float2 unpack2(u64 v) {
    float2 f; asm("mov.b64 {%0, %1}, %2;" : "=f"(f.x), "=f"(f.y) : "l"(v)); return f;
}
__device__ __forceinline__ u64 ffma2(u64 a, u64 b, u64 c) {
    u64 d; asm("fma.rn.f32x2 %0, %1, %2, %3;" : "=l"(d) : "l"(a), "l"(b), "l"(c)); return d;
}
__device__ __forceinline__ u64 mul2(u64 a, u64 b) {
    u64 d; asm("mul.rn.f32x2 %0, %1, %2;" : "=l"(d) : "l"(a), "l"(b)); return d;
}

__device__ __forceinline__ float leaky1(float s) {
    return fmaxf(s, 0.01f * s);
}

__device__ __forceinline__ int binof(float v) {
    int t = (int)floorf((v + 1.0f) * 128.0f);
    t = max(t, 0); t = min(t, 255);
    return t;
}

// delta = x - clip(pred,-1,1); torch fmod(delta+1,2)-1 with t in [-1,3]
__device__ __forceinline__ float wrapdelta(float xv, float pred) {
    float p = fminf(fmaxf(pred, -1.0f), 1.0f);
    float t = (xv - p) + 1.0f;
    t = (t >= 2.0f) ? (t - 2.0f) : t;
    return t - 1.0f;
}

struct __align__(16) Smem {
    float W0t[16 * 12 * 16];  // [k][o][j], zero at j==k (3072)
    float W1t[16 * 12 * 12];  // [k][o][i] transposed (2304)
    float W2t[16 * 12 * 12];  // (2304)
    float W3v[16 * 12];       // [k][i] (natural layout already a vector)
    float b0s[16 * 12];
    float b1s[16 * 12];
    float b2s[16 * 12];
    float b3s[16];
    unsigned int hx[256];
    unsigned int hd[256];
    float warpsums[8];
};

__global__ void __launch_bounds__(TPB, 2) codec_main(
    const float* __restrict__ x,
    const float* __restrict__ W0, const float* __restrict__ b0,
    const float* __restrict__ W1, const float* __restrict__ b1,
    const float* __restrict__ W2, const float* __restrict__ b2,
    const float* __restrict__ W3, const float* __restrict__ b3)
{
    __shared__ Smem s;
    const int tid = threadIdx.x;
    const int bc = blockIdx.x / CHUNKS;     // 0..47  (= b*3 + c)
    const int chunk = blockIdx.x % CHUNKS;
    const int c = bc % 3;

    // ---- transpose-load weights into smem ----
    // W0t[k][o][j]: zero at j==k; else W0[c][k][ j-(j>k) ][o]
    for (int idx = tid; idx < 16 * 12 * 16; idx += TPB) {
        int k = idx / 192; int r = idx % 192; int o = r / 16; int j = r % 16;
        float w = 0.0f;
        if (j != k) {
            int i = j - (j > k);
            w = W0[((c * 16 + k) * 15 + i) * 12 + o];
        }
        s.W0t[idx] = w;
    }
    // W1t/W2t[k][o][i] = W[c][k][i][o]
    for (int idx = tid; idx < 16 * 12 * 12; idx += TPB) {
        int k = idx / 144; int r = idx % 144; int o = r / 12; int i = r % 12;
        s.W1t[idx] = W1[c * 2304 + k * 144 + i * 12 + o];
        s.W2t[idx] = W2[c * 2304 + k * 144 + i * 12 + o];
    }
    for (int idx = tid; idx < 192; idx += TPB) {
        s.W3v[idx] = W3[c * 192 + idx];   // [k][i][0] -> [k][i]
        s.b0s[idx] = b0[c * 192 + idx];
        s.b1s[idx] = b1[c * 192 + idx];
        s.b2s[idx] = b2[c * 192 + idx];
    }
    if (tid < 16) s.b3s[tid] = b3[c * 16 + tid];
    s.hx[tid] = 0;
    s.hd[tid] = 0;
    __syncthreads();

    // ---- load 2 blocks of 16 pixels as 8 adjacent-pixel pairs each ----
    const float* xb = x + (size_t)bc * (1024 * 1024);
    const int n0 = chunk * BLOCKS_PER_CTA + tid;
    const int n1 = n0 + TPB;
    const float* pA = xb + ((n0 >> 8) * 4096) + ((n0 & 255) * 4);
    const float* pB = xb + ((n1 >> 8) * 4096) + ((n1 & 255) * 4);

    u64 vpA[8], vpB[8];
#pragma unroll
    for (int r = 0; r < 4; r++) {
        ulonglong2 a = *(const ulonglong2*)(pA + r * 1024);  // (x0,x1),(x2,x3)
        ulonglong2 b = *(const ulonglong2*)(pB + r * 1024);
        vpA[r * 2 + 0] = a.x; vpA[r * 2 + 1] = a.y;
        vpB[r * 2 + 0] = b.x; vpB[r * 2 + 1] = b.y;
    }

    // ---- histogram of raw x ----
#pragma unroll
    for (int jp = 0; jp < 8; jp++) {
        float2 fa = unpack2(vpA[jp]);
        float2 fb = unpack2(vpB[jp]);
        atomicAdd(&s.hx[binof(fa.x)], 1u);
        atomicAdd(&s.hx[binof(fa.y)], 1u);
        atomicAdd(&s.hx[binof(fb.x)], 1u);
        atomicAdd(&s.hx[binof(fb.y)], 1u);
    }

    // ---- autoregressive 16-step MLP chain ----
    float sq = 0.0f;
#pragma unroll 1
    for (int k = 0; k < 16; k++) {
        const float* W0k = s.W0t + k * 192;
        const float* W1k = s.W1t + k * 144;
        const float* W2k = s.W2t + k * 144;

        u64 accA[12], accB[12];
        u64 hA[6], hB[6];

        // ---- layer 0: 16 inputs (8 pairs, zero row at j==k) x 12 outputs ----
#pragma unroll
        for (int o = 0; o < 12; o++) {
            const ulonglong2* wr = (const ulonglong2*)(W0k + o * 16);
            ulonglong2 wa = wr[0], wb = wr[1], wc = wr[2], wd = wr[3];
            u64 aA = mul2(wa.x, vpA[0]);
            u64 aB = mul2(wa.x, vpB[0]);
            aA = ffma2(wa.y, vpA[1], aA);  aB = ffma2(wa.y, vpB[1], aB);
            aA = ffma2(wb.x, vpA[2], aA);  aB = ffma2(wb.x, vpB[2], aB);
            aA = ffma2(wb.y, vpA[3], aA);  aB = ffma2(wb.y, vpB[3], aB);
            aA = ffma2(wc.x, vpA[4], aA);  aB = ffma2(wc.x, vpB[4], aB);
            aA = ffma2(wc.y, vpA[5], aA);  aB = ffma2(wc.y, vpB[5], aB);
            aA = ffma2(wd.x, vpA[6], aA);  aB = ffma2(wd.x, vpB[6], aB);
            aA = ffma2(wd.y, vpA[7], aA);  aB = ffma2(wd.y, vpB[7], aB);
            accA[o] = aA; accB[o] = aB;
        }
        {
            const float4* bp = (const float4*)(s.b0s + k * 12);
            float4 q0 = bp[0], q1 = bp[1], q2 = bp[2];
            float bb[12] = {q0.x, q0.y, q0.z, q0.w, q1.x, q1.y, q1.z, q1.w,
                            q2.x, q2.y, q2.z, q2.w};
#pragma unroll
            for (int p = 0; p < 6; p++) {
                float2 a0 = unpack2(accA[2 * p]), a1 = unpack2(accA[2 * p + 1]);
                hA[p] = pack2(leaky1(a0.x + a0.y + bb[2 * p]),
                              leaky1(a1.x + a1.y + bb[2 * p + 1]));
                float2 c0 = unpack2(accB[2 * p]), c1 = unpack2(accB[2 * p + 1]);
                hB[p] = pack2(leaky1(c0.x + c0.y + bb[2 * p]),
                              leaky1(c1.x + c1.y + bb[2 * p + 1]));
            }
        }

        // ---- layer 1: 12 x 12 ----
#pragma unroll
        for (int o = 0; o < 12; o++) {
            const ulonglong2* wr = (const ulonglong2*)(W1k + o * 12);
            ulonglong2 wa = wr[0], wb = wr[1];
            u64 wc_ = *(const u64*)(W1k + o * 12 + 8);
            u64 wd_ = *(const u64*)(W1k + o * 12 + 10);
            u64 aA = mul2(wa.x, hA[0]);
            u64 aB = mul2(wa.x, hB[0]);
            aA = ffma2(wa.y, hA[1], aA);  aB = ffma2(wa.y, hB[1], aB);
            aA = ffma2(wb.x, hA[2], aA);  aB = ffma2(wb.x, hB[2], aB);
            aA = ffma2(wb.y, hA[3], aA);  aB = ffma2(wb.y, hB[3], aB);
            aA = ffma2(wc_, hA[4], aA);   aB = ffma2(wc_, hB[4], aB);
            aA = ffma2(wd_, hA[5], aA);   aB = ffma2(wd_, hB[5], aB);
            accA[o] = aA; accB[o] = aB;
        }
        {
            const float4* bp = (const float4*)(s.b1s + k * 12);
            float4 q0 = bp[0], q1 = bp[1], q2 = bp[2];
            float bb[12] = {q0.x, q0.y, q0.z, q0.w, q1.x, q1.y, q1.z, q1.w,
                            q2.x, q2.y, q2.z, q2.w};
#pragma unroll
            for (int p = 0; p < 6; p++) {
                float2 a0 = unpack2(accA[2 * p]), a1 = unpack2(accA[2 * p + 1]);
                hA[p] = pack2(leaky1(a0.x + a0.y + bb[2 * p]),
                              leaky1(a1.x + a1.y + bb[2 * p + 1]));
                float2 c0 = unpack2(accB[2 * p]), c1 = unpack2(accB[2 * p + 1]);
                hB[p] = pack2(leaky1(c0.x + c0.y + bb[2 * p]),
                              leaky1(c1.x + c1.y + bb[2 * p + 1]));
            }
        }

        // ---- layer 2: 12 x 12 ----
#pragma unroll
        for (int o = 0; o < 12; o++) {
            const ulonglong2* wr = (const ulonglong2*)(W2k + o * 12);
            ulonglong2 wa = wr[0], wb = wr[1];
            u64 wc_ = *(const u64*)(W2k + o * 12 + 8);
            u64 wd_ = *(const u64*)(W2k + o * 12 + 10);
            u64 aA = mul2(wa.x, hA[0]);
            u64 aB = mul2(wa.x, hB[0]);
            aA = ffma2(wa.y, hA[1], aA);  aB = ffma2(wa.y, hB[1], aB);
            aA = ffma2(wb.x, hA[2], aA);  aB = ffma2(wb.x, hB[2], aB);
            aA = ffma2(wb.y, hA[3], aA);  aB = ffma2(wb.y, hB[3], aB);
            aA = ffma2(wc_, hA[4], aA);   aB = ffma2(wc_, hB[4], aB);
            aA = ffma2(wd_, hA[5], aA);   aB = ffma2(wd_, hB[5], aB);
            accA[o] = aA; accB[o] = aB;
        }
        {
            const float4* bp = (const float4*)(s.b2s + k * 12);
            float4 q0 = bp[0], q1 = bp[1], q2 = bp[2];
            float bb[12] = {q0.x, q0.y, q0.z, q0.w, q1.x, q1.y, q1.z, q1.w,
                            q2.x, q2.y, q2.z, q2.w};
#pragma unroll
            for (int p = 0; p < 6; p++) {
                float2 a0 = unpack2(accA[2 * p]), a1 = unpack2(accA[2 * p + 1]);
                hA[p] = pack2(leaky1(a0.x + a0.y + bb[2 * p]),
                              leaky1(a1.x + a1.y + bb[2 * p + 1]));
                float2 c0 = unpack2(accB[2 * p]), c1 = unpack2(accB[2 * p + 1]);
                hB[p] = pack2(leaky1(c0.x + c0.y + bb[2 * p]),
                              leaky1(c1.x + c1.y + bb[2 * p + 1]));
            }
        }

        // ---- layer 3: 12 -> 1 ----
        float predA, predB;
        {
            const ulonglong2* wr = (const ulonglong2*)(s.W3v + k * 12);
            ulonglong2 wa = wr[0], wb = wr[1];
            u64 wc_ = *(const u64*)(s.W3v + k * 12 + 8);
            u64 wd_ = *(const u64*)(s.W3v + k * 12 + 10);
            u64 aA = mul2(wa.x, hA[0]);
            u64 aB = mul2(wa.x, hB[0]);
            aA = ffma2(wa.y, hA[1], aA);  aB = ffma2(wa.y, hB[1], aB);
            aA = ffma2(wb.x, hA[2], aA);  aB = ffma2(wb.x, hB[2], aB);
            aA = ffma2(wb.y, hA[3], aA);  aB = ffma2(wb.y, hB[3], aB);
            aA = ffma2(wc_, hA[4], aA);   aB = ffma2(wc_, hB[4], aB);
            aA = ffma2(wd_, hA[5], aA);   aB = ffma2(wd_, hB[5], aB);
            float b3s = s.b3s[k];
            float2 fA = unpack2(aA);
            float2 fB = unpack2(aB);
            predA = fA.x + fA.y + b3s;
            predB = fB.x + fB.y + b3s;
        }

        // ---- delta, hist, writeback ----
        const int kp = k >> 1;
        const int kh = k & 1;

        u64 xpA = vpA[0], xpB = vpB[0];
#pragma unroll
        for (int jp = 1; jp < 8; jp++) if (jp == kp) { xpA = vpA[jp]; xpB = vpB[jp]; }
        float2 xfA = unpack2(xpA);
        float2 xfB = unpack2(xpB);
        float xkA = kh ? xfA.y : xfA.x;
        float xkB = kh ? xfB.y : xfB.x;

        float eA = wrapdelta(xkA, predA);
        float eB = wrapdelta(xkB, predB);
        sq += eA * eA + eB * eB;
        atomicAdd(&s.hd[binof(eA)], 1u);
        atomicAdd(&s.hd[binof(eB)], 1u);

        u64 npA = kh ? pack2(xfA.x, eA) : pack2(eA, xfA.y);
        u64 npB = kh ? pack2(xfB.x, eB) : pack2(eB, xfB.y);
#pragma unroll
        for (int jp = 0; jp < 8; jp++) if (jp == kp) { vpA[jp] = npA; vpB[jp] = npB; }
    }

    // ---- reductions ----
#pragma unroll
    for (int off = 16; off; off >>= 1) sq += __shfl_xor_sync(0xFFFFFFFFu, sq, off);
    if ((tid & 31) == 0) s.warpsums[tid >> 5] = sq;
    __syncthreads();
    if (tid == 0) {
        float t = 0.0f;
#pragma unroll
        for (int w = 0; w < 8; w++) t += s.warpsums[w];
        atomicAdd(&g_sumsq, (double)t);
    }
    atomicAdd(&g_hist_x[bc * 256 + tid], s.hx[tid]);
    atomicAdd(&g_hist_d[bc * 256 + tid], s.hd[tid]);
}

__global__ void codec_zero() {
    int t = blockIdx.x * blockDim.x + threadIdx.x;
    if (t < NBC * 256) { g_hist_x[t] = 0; g_hist_d[t] = 0; }
    if (t == 0) g_sumsq = 0.0;
}

__global__ void codec_final(float* __restrict__ out) {
    __shared__ double red[256];
    const int t = threadIdx.x;
    const float invres = 1.0f / 1048576.0f;
    double ex = 0.0, ed = 0.0;
    for (int i = t; i < NBC * 256; i += 256) {
        float px = (float)g_hist_x[i] * invres;
        if (px > 0.0f) ex += (double)(-px * log2f(px));
        float pd = (float)g_hist_d[i] * invres;
        if (pd > 0.0f) ed += (double)(-pd * log2f(pd));
    }
    red[t] = ex;
    __syncthreads();
    for (int sft = 128; sft; sft >>= 1) {
        if (t < sft) red[t] += red[t + sft];
        __syncthreads();
    }
    double entx = red[0];
    __syncthreads();
    red[t] = ed;
    __syncthreads();
    for (int sft = 128; sft; sft >>= 1) {
        if (t < sft) red[t] += red[t + sft];
        __syncthreads();
    }
    double entd = red[0];
    if (t == 0) {
        double mean = g_sumsq / 50331648.0;   // 16*3*65536*16
        out[0] = 255.0f * (float)sqrt(mean);
        out[1] = (float)(entx / 384.0);       // 8 * nch, nch=48
        out[2] = (float)(entd / 384.0);
    }
}

extern "C" void kernel_launch(void* const* d_in, const int* in_sizes, int n_in,
                              void* d_out, int out_size) {
    const float* x  = (const float*)d_in[0];
    const float* W0 = (const float*)d_in[1];
    const float* b0 = (const float*)d_in[2];
    const float* W1 = (const float*)d_in[3];
    const float* b1 = (const float*)d_in[4];
    const float* W2 = (const float*)d_in[5];
    const float* b2 = (const float*)d_in[6];
    const float* W3 = (const float*)d_in[7];
    const float* b3 = (const float*)d_in[8];

    codec_zero<<<NBC, 256>>>();
    codec_main<<<NBC * CHUNKS, TPB>>>(x, W0, b0, W1, b1, W2, b2, W3, b3);
    codec_final<<<1, 256>>>((float*)d_out);
}